// round 1
// baseline (speedup 1.0000x reference)
#include <cuda_runtime.h>
#include <cuda_bf16.h>

// Problem shapes (fixed by the reference):
//   z:       [B=16, L=16, H=64, W=64] float32
//   codes_w: [L=16, C=64]             float32
// Outputs (flattened into d_out as float32, in reference return order):
//   soft_symbols [B,H,W,L], hard_symbols [B,H,W,L], idxes [B,H,W,L]
#define B_ 16
#define L_ 16
#define H_ 64
#define W_ 64
#define C_ 64
#define N_TOTAL (B_ * L_ * H_ * W_)   // 1,048,576

__global__ __launch_bounds__(256, 8)
void soft_to_hard_kernel(const float* __restrict__ z,
                         const float* __restrict__ codes,
                         float* __restrict__ out)
{
    __shared__ float s_codes[L_ * C_];   // 4 KB, whole codebook
    {
        int t = threadIdx.x;
        #pragma unroll
        for (int k = 0; k < (L_ * C_) / 256; ++k)
            s_codes[t + k * 256] = codes[t + k * 256];
    }
    __syncthreads();

    // Linear index over z layout (b, l, h, w) -> coalesced z read,
    // and uniform l per warp (W=64 >= 32) -> broadcast LDS on code row.
    int i = blockIdx.x * 256 + threadIdx.x;

    int w = i & (W_ - 1);
    int t = i >> 6;           // / W_
    int h = t & (H_ - 1);
    t >>= 6;                  // / H_
    int l = t & (L_ - 1);
    int b = t >> 4;           // / L_

    float zv = z[i];
    const float* __restrict__ cw = &s_codes[l * C_];

    // Softmin over codes == softmax(-d). d >= 0 so exp(-d) <= 1: no max-sub needed.
    float sum  = 0.0f;
    float acc  = 0.0f;
    float dmin = 3.402823466e38f;
    int   imin = 0;

    #pragma unroll
    for (int c = 0; c < C_; ++c) {
        float cv = cw[c];
        float d  = fabsf(zv - cv);
        float e  = __expf(-d);          // MUFU EX2 path
        sum += e;
        acc  = fmaf(e, cv, acc);
        if (d < dmin) { dmin = d; imin = c; }   // strict '<' = first-min tiebreak
    }

    // Output layout [B, H, W, L]
    int oi = ((b * H_ + h) * W_ + w) * L_ + l;

    out[oi]                 = __fdividef(acc, sum);  // soft_symbols
    out[N_TOTAL + oi]       = cw[imin];              // hard_symbols
    out[2 * N_TOTAL + oi]   = (float)imin;           // idxes (as float in f32 out buffer)
}

extern "C" void kernel_launch(void* const* d_in, const int* in_sizes, int n_in,
                              void* d_out, int out_size)
{
    const float* z     = (const float*)d_in[0];
    const float* codes = (const float*)d_in[1];
    float* out         = (float*)d_out;

    dim3 grid(N_TOTAL / 256);
    dim3 block(256);
    soft_to_hard_kernel<<<grid, block>>>(z, codes, out);
}